// round 11
// baseline (speedup 1.0000x reference)
#include <cuda_runtime.h>

// out[b,q,d] = sum_k values[b,k,d]  (softmax over singleton axis == 1;
// queries/keys/w_score are dead code). B=4, Q=512, K=512, F=128.
//
// FINAL — converged and replicated (R9: 4.77us kernel / 6.66us wall,
// R10 identical source: 4.74 / 6.62). Session evidence:
//  * wall is pinned at a ~6.6us graph-replay floor, insensitive to kernel
//    dur below ~6.3us (R2 kernel 6.24us -> same wall as R9 kernel 4.77us)
//  * feature-split 128 blocks x 256 threads is the measured optimum:
//    512 load-wavefronts/block (floor for a full-K column sum),
//    8 warps/SM avoids cross-warp L1tex queue contention (R7 regression),
//    cross-block sync / 2-kernel variants measured strictly worse (R1/R4).
// Block = (batch, 32-float feature slice, 64-row Q slice). Single barrier.

#define B_   4
#define Q_   512
#define K_   512
#define F4   32      // float4 per full feature row
#define FSL4 8       // float4 per feature slice (32 floats = 128 B)
#define QROWS 64     // Q rows written per block

__global__ void __launch_bounds__(256, 1)
feat_split_sum_broadcast(const float4* __restrict__ values,
                         float4* __restrict__ out) {
    __shared__ float4 part[8][FSL4];           // per-warp column partials (1 KB)

    const int b   = blockIdx.x >> 5;           // batch         (0..3)
    const int rem = blockIdx.x & 31;
    const int fsl = rem >> 3;                  // feature slice (0..3)
    const int qsl = rem & 7;                   // Q slice       (0..7)

    const int tid  = threadIdx.x;
    const int w    = tid >> 5;                 // warp 0..7: K rows [w*64, +64)
    const int lane = tid & 31;
    const int c    = lane & 7;                 // float4 column within slice
    const int rsub = lane >> 3;                // row offset 0..3 in 4-row group

    // Hoist the output address above the load/barrier chain.
    // Thread writes rows (tid/8) and (tid/8 + 32) of its 64-row Q slice.
    const int row0 = qsl * QROWS + (tid >> 3);
    float4* const ob = out + ((size_t)(b * Q_ + row0)) * F4 + fsl * FSL4 + c;

    // ---- Phase 1: each lane streams 16 rows (stride 4) of its 16B column.
    const float4* p = values
        + ((size_t)(b * K_ + w * 64 + rsub)) * F4 + fsl * FSL4 + c;

    float4 a0 = make_float4(0.f,0.f,0.f,0.f);
    float4 a1 = a0, a2 = a0, a3 = a0;
#pragma unroll
    for (int i = 0; i < 16; i += 4) {
        float4 v0 = __ldcg(p + (i + 0) * 4 * F4);
        float4 v1 = __ldcg(p + (i + 1) * 4 * F4);
        float4 v2 = __ldcg(p + (i + 2) * 4 * F4);
        float4 v3 = __ldcg(p + (i + 3) * 4 * F4);
        a0.x += v0.x; a0.y += v0.y; a0.z += v0.z; a0.w += v0.w;
        a1.x += v1.x; a1.y += v1.y; a1.z += v1.z; a1.w += v1.w;
        a2.x += v2.x; a2.y += v2.y; a2.z += v2.z; a2.w += v2.w;
        a3.x += v3.x; a3.y += v3.y; a3.z += v3.z; a3.w += v3.w;
    }
    float4 acc;
    acc.x = (a0.x + a1.x) + (a2.x + a3.x);
    acc.y = (a0.y + a1.y) + (a2.y + a3.y);
    acc.z = (a0.z + a1.z) + (a2.z + a3.z);
    acc.w = (a0.w + a1.w) + (a2.w + a3.w);

    // ---- Phase 2: fold the 4 row-groups sharing a column (xor 8, 16).
#pragma unroll
    for (int m = 8; m <= 16; m <<= 1) {
        acc.x += __shfl_xor_sync(0xffffffffu, acc.x, m);
        acc.y += __shfl_xor_sync(0xffffffffu, acc.y, m);
        acc.z += __shfl_xor_sync(0xffffffffu, acc.z, m);
        acc.w += __shfl_xor_sync(0xffffffffu, acc.w, m);
    }
    if (lane < FSL4) part[w][lane] = acc;
    __syncthreads();

    // ---- Phase 3: fold 8 warp-partials (broadcast LDS, conflict-free).
    float4 s0 = part[0][c], s1 = part[1][c], s2 = part[2][c], s3 = part[3][c];
    {
        float4 w0 = part[4][c], w1 = part[5][c], w2 = part[6][c], w3 = part[7][c];
        s0.x += w0.x; s0.y += w0.y; s0.z += w0.z; s0.w += w0.w;
        s1.x += w1.x; s1.y += w1.y; s1.z += w1.z; s1.w += w1.w;
        s2.x += w2.x; s2.y += w2.y; s2.z += w2.z; s2.w += w2.w;
        s3.x += w3.x; s3.y += w3.y; s3.z += w3.z; s3.w += w3.w;
    }
    float4 t;
    t.x = (s0.x + s1.x) + (s2.x + s3.x);
    t.y = (s0.y + s1.y) + (s2.y + s3.y);
    t.z = (s0.z + s1.z) + (s2.z + s3.z);
    t.w = (s0.w + s1.w) + (s2.w + s3.w);

    // ---- Phase 4: two coalesced STG.128 per thread (rows r0 and r0+32).
    ob[0]       = t;
    ob[32 * F4] = t;
}

extern "C" void kernel_launch(void* const* d_in, const int* in_sizes, int n_in,
                              void* d_out, int out_size) {
    // inputs (metadata order): queries, keys, values, w_score
    const float4* values = (const float4*)d_in[2];
    float4* out = (float4*)d_out;
    feat_split_sum_broadcast<<<128, 256>>>(values, out);
}

// round 12
// speedup vs baseline: 1.0483x; 1.0483x over previous
#include <cuda_runtime.h>

// out[b,q,d] = sum_k values[b,k,d]  (softmax over singleton axis == 1;
// queries/keys/w_score are dead code). B=4, Q=512, K=512, F=128.
//
// FINAL — converged, triple-replicated (R9/R10/R11 identical source:
// kernel 4.77/4.74/4.90us, wall 6.66/6.62/6.94us, rel_err bit-identical).
// Session evidence:
//  * wall pinned at ~6.6us graph-replay floor (R2 kernel 6.24us -> same
//    wall as R9 kernel 4.77us); kernel is ~1.8us under the floor
//  * 512 load-wavefronts/block is the decomposition's hard floor (full-K
//    sum per output, cross-block partials measured +1.5us in R4)
//  * 8 warps/block measured optimal: 8w(4.8) < 16w(5.2) < 32w(6.0) —
//    cross-warp L1tex queue contention ordering
// Block = (batch, 32-float feature slice, 64-row Q slice). Single barrier.

#define B_   4
#define Q_   512
#define K_   512
#define F4   32      // float4 per full feature row
#define FSL4 8       // float4 per feature slice (32 floats = 128 B)
#define QROWS 64     // Q rows written per block

__global__ void __launch_bounds__(256, 1)
feat_split_sum_broadcast(const float4* __restrict__ values,
                         float4* __restrict__ out) {
    __shared__ float4 part[8][FSL4];           // per-warp column partials (1 KB)

    const int b   = blockIdx.x >> 5;           // batch         (0..3)
    const int rem = blockIdx.x & 31;
    const int fsl = rem >> 3;                  // feature slice (0..3)
    const int qsl = rem & 7;                   // Q slice       (0..7)

    const int tid  = threadIdx.x;
    const int w    = tid >> 5;                 // warp 0..7: K rows [w*64, +64)
    const int lane = tid & 31;
    const int c    = lane & 7;                 // float4 column within slice
    const int rsub = lane >> 3;                // row offset 0..3 in 4-row group

    // Hoist the output address above the load/barrier chain.
    // Thread writes rows (tid/8) and (tid/8 + 32) of its 64-row Q slice.
    const int row0 = qsl * QROWS + (tid >> 3);
    float4* const ob = out + ((size_t)(b * Q_ + row0)) * F4 + fsl * FSL4 + c;

    // ---- Phase 1: each lane streams 16 rows (stride 4) of its 16B column.
    const float4* p = values
        + ((size_t)(b * K_ + w * 64 + rsub)) * F4 + fsl * FSL4 + c;

    float4 a0 = make_float4(0.f,0.f,0.f,0.f);
    float4 a1 = a0, a2 = a0, a3 = a0;
#pragma unroll
    for (int i = 0; i < 16; i += 4) {
        float4 v0 = __ldcg(p + (i + 0) * 4 * F4);
        float4 v1 = __ldcg(p + (i + 1) * 4 * F4);
        float4 v2 = __ldcg(p + (i + 2) * 4 * F4);
        float4 v3 = __ldcg(p + (i + 3) * 4 * F4);
        a0.x += v0.x; a0.y += v0.y; a0.z += v0.z; a0.w += v0.w;
        a1.x += v1.x; a1.y += v1.y; a1.z += v1.z; a1.w += v1.w;
        a2.x += v2.x; a2.y += v2.y; a2.z += v2.z; a2.w += v2.w;
        a3.x += v3.x; a3.y += v3.y; a3.z += v3.z; a3.w += v3.w;
    }
    float4 acc;
    acc.x = (a0.x + a1.x) + (a2.x + a3.x);
    acc.y = (a0.y + a1.y) + (a2.y + a3.y);
    acc.z = (a0.z + a1.z) + (a2.z + a3.z);
    acc.w = (a0.w + a1.w) + (a2.w + a3.w);

    // ---- Phase 2: fold the 4 row-groups sharing a column (xor 8, 16).
#pragma unroll
    for (int m = 8; m <= 16; m <<= 1) {
        acc.x += __shfl_xor_sync(0xffffffffu, acc.x, m);
        acc.y += __shfl_xor_sync(0xffffffffu, acc.y, m);
        acc.z += __shfl_xor_sync(0xffffffffu, acc.z, m);
        acc.w += __shfl_xor_sync(0xffffffffu, acc.w, m);
    }
    if (lane < FSL4) part[w][lane] = acc;
    __syncthreads();

    // ---- Phase 3: fold 8 warp-partials (broadcast LDS, conflict-free).
    float4 s0 = part[0][c], s1 = part[1][c], s2 = part[2][c], s3 = part[3][c];
    {
        float4 w0 = part[4][c], w1 = part[5][c], w2 = part[6][c], w3 = part[7][c];
        s0.x += w0.x; s0.y += w0.y; s0.z += w0.z; s0.w += w0.w;
        s1.x += w1.x; s1.y += w1.y; s1.z += w1.z; s1.w += w1.w;
        s2.x += w2.x; s2.y += w2.y; s2.z += w2.z; s2.w += w2.w;
        s3.x += w3.x; s3.y += w3.y; s3.z += w3.z; s3.w += w3.w;
    }
    float4 t;
    t.x = (s0.x + s1.x) + (s2.x + s3.x);
    t.y = (s0.y + s1.y) + (s2.y + s3.y);
    t.z = (s0.z + s1.z) + (s2.z + s3.z);
    t.w = (s0.w + s1.w) + (s2.w + s3.w);

    // ---- Phase 4: two coalesced STG.128 per thread (rows r0 and r0+32).
    ob[0]       = t;
    ob[32 * F4] = t;
}

extern "C" void kernel_launch(void* const* d_in, const int* in_sizes, int n_in,
                              void* d_out, int out_size) {
    // inputs (metadata order): queries, keys, values, w_score
    const float4* values = (const float4*)d_in[2];
    float4* out = (float4*)d_out;
    feat_split_sum_broadcast<<<128, 256>>>(values, out);
}